// round 3
// baseline (speedup 1.0000x reference)
#include <cuda_runtime.h>

// Problem constants (match reference setup_inputs)
#define NTOK   8192      // 4 * 2048
#define DMODEL 512
#define NEXP   64
#define HEXP   256
#define HSH    512       // H * NSH
#define CAP    1024
#define RSCALE 2.5f

typedef unsigned long long u64;

// ---- packed f32x2 helpers (Blackwell FFMA2 path, PTX-only) --------------------
__device__ __forceinline__ u64 bcast2(float x) {
    u64 d;
    asm("mov.b64 %0, {%1, %1};" : "=l"(d) : "r"(__float_as_uint(x)));
    return d;
}
__device__ __forceinline__ void fma2(u64& d, u64 a, u64 b) {
    asm("fma.rn.f32x2 %0, %1, %2, %0;" : "+l"(d) : "l"(a), "l"(b));
}
__device__ __forceinline__ float2 unpack2(u64 v) {
    float2 f;
    asm("mov.b64 {%0, %1}, %2;" : "=f"(f.x), "=f"(f.y) : "l"(v));
    return f;
}
__device__ __forceinline__ float silu_f(float z) {
    return z / (1.f + __expf(-z));
}

// ---------------- scratch (device globals; no allocations allowed) -------------
__device__ int   g_cnt[NEXP];
__device__ int   g_tok[NEXP * CAP];
__device__ float g_wgt[NEXP * CAP];
__device__ float g_h [(size_t)NEXP * CAP * HEXP];   // routed hidden
__device__ float g_hs[(size_t)NTOK * HSH];          // shared-expert hidden

// ---------------- k0: zero per-expert counters --------------------------------
__global__ void k_zero() {
    if (threadIdx.x < NEXP) g_cnt[threadIdx.x] = 0;
}

// ---------------- k1: router + dispatch ----------------------------------------
#define RTB 16
__global__ void k_router(const float* __restrict__ x, const float* __restrict__ gw) {
    __shared__ __align__(16) float xs[RTB][DMODEL];
    __shared__ float sc[RTB][NEXP];
    const int tid = threadIdx.x;
    const int t0  = blockIdx.x * RTB;

    const float4* src = (const float4*)(x + (size_t)t0 * DMODEL);
    float4* dst = (float4*)&xs[0][0];
    #pragma unroll
    for (int i = tid; i < RTB * DMODEL / 4; i += 128) dst[i] = src[i];
    __syncthreads();

    const int e    = tid & 63;
    const int half = tid >> 6;
    const float* g = gw + (size_t)e * DMODEL;

    float acc[8];
    #pragma unroll
    for (int j = 0; j < 8; ++j) acc[j] = 0.f;

    for (int d = 0; d < DMODEL; d += 4) {
        const float4 gv = *(const float4*)(g + d);
        #pragma unroll
        for (int j = 0; j < 8; ++j) {
            const int tt = half * 8 + j;
            acc[j] = fmaf(gv.x, xs[tt][d],     acc[j]);
            acc[j] = fmaf(gv.y, xs[tt][d + 1], acc[j]);
            acc[j] = fmaf(gv.z, xs[tt][d + 2], acc[j]);
            acc[j] = fmaf(gv.w, xs[tt][d + 3], acc[j]);
        }
    }
    #pragma unroll
    for (int j = 0; j < 8; ++j)
        sc[half * 8 + j][e] = 1.f / (1.f + __expf(-acc[j]));
    __syncthreads();

    if (tid < RTB) {
        const int t = t0 + tid;
        float s0 = -1.f, s1 = -1.f; int e0 = 0, e1 = 0;
        #pragma unroll 8
        for (int i = 0; i < NEXP; ++i) {
            const float s = sc[tid][i];
            if (s > s0)      { s1 = s0; e1 = e0; s0 = s; e0 = i; }
            else if (s > s1) { s1 = s;  e1 = i; }
        }
        const float inv = RSCALE / (s0 + s1 + 1e-20f);
        const float w0 = s0 * inv, w1 = s1 * inv;
        int p0 = atomicAdd(&g_cnt[e0], 1);
        if (p0 < CAP) { g_tok[e0 * CAP + p0] = t; g_wgt[e0 * CAP + p0] = w0; }
        int p1 = atomicAdd(&g_cnt[e1], 1);
        if (p1 < CAP) { g_tok[e1 * CAP + p1] = t; g_wgt[e1 * CAP + p1] = w1; }
    }
}

// ================================================================================
// Dual-operand SwiGLU GEMM (FFN1), FFMA2 path.
// Tile: 128 rows x 64 cols, BK=16, 256 threads, microtile 8x4 per thread, x2 ops.
// ================================================================================

// ---------------- shared expert FFN1: g_hs = silu(X@sw1) * (X@sw3) -------------
__global__ __launch_bounds__(256) void k_sffn1(const float* __restrict__ X,
                                               const float* __restrict__ W1g,
                                               const float* __restrict__ W3g) {
    __shared__ __align__(16) float As [16][128];
    __shared__ __align__(16) float Bs1[16][64];
    __shared__ __align__(16) float Bs3[16][64];
    const int tid = threadIdx.x;
    const int m0 = blockIdx.x * 128, n0 = blockIdx.y * 64;
    const int ar = tid >> 1, ac = (tid & 1) * 8;
    const int br = tid >> 4, bc = (tid & 15) * 4;
    const int ty = tid >> 4, tx = tid & 15;

    u64 acc1[8][2], acc3[8][2];
    #pragma unroll
    for (int i = 0; i < 8; ++i) {
        acc1[i][0] = 0ULL; acc1[i][1] = 0ULL;
        acc3[i][0] = 0ULL; acc3[i][1] = 0ULL;
    }

    for (int k0 = 0; k0 < DMODEL; k0 += 16) {
        const float4 a0 = *(const float4*)(X + (size_t)(m0 + ar) * DMODEL + k0 + ac);
        const float4 a1 = *(const float4*)(X + (size_t)(m0 + ar) * DMODEL + k0 + ac + 4);
        As[ac + 0][ar] = a0.x; As[ac + 1][ar] = a0.y; As[ac + 2][ar] = a0.z; As[ac + 3][ar] = a0.w;
        As[ac + 4][ar] = a1.x; As[ac + 5][ar] = a1.y; As[ac + 6][ar] = a1.z; As[ac + 7][ar] = a1.w;
        *(float4*)&Bs1[br][bc] = *(const float4*)(W1g + (size_t)(k0 + br) * HSH + n0 + bc);
        *(float4*)&Bs3[br][bc] = *(const float4*)(W3g + (size_t)(k0 + br) * HSH + n0 + bc);
        __syncthreads();
        #pragma unroll
        for (int k = 0; k < 16; ++k) {
            const float4 av0 = *(const float4*)&As[k][ty * 8];
            const float4 av1 = *(const float4*)&As[k][ty * 8 + 4];
            u64 ap[8];
            ap[0] = bcast2(av0.x); ap[1] = bcast2(av0.y); ap[2] = bcast2(av0.z); ap[3] = bcast2(av0.w);
            ap[4] = bcast2(av1.x); ap[5] = bcast2(av1.y); ap[6] = bcast2(av1.z); ap[7] = bcast2(av1.w);
            const ulonglong2 b1 = *(const ulonglong2*)&Bs1[k][tx * 4];
            const ulonglong2 b3 = *(const ulonglong2*)&Bs3[k][tx * 4];
            #pragma unroll
            for (int i = 0; i < 8; ++i) {
                fma2(acc1[i][0], ap[i], b1.x);
                fma2(acc1[i][1], ap[i], b1.y);
                fma2(acc3[i][0], ap[i], b3.x);
                fma2(acc3[i][1], ap[i], b3.y);
            }
        }
        __syncthreads();
    }
    #pragma unroll
    for (int i = 0; i < 8; ++i) {
        const float2 z1a = unpack2(acc1[i][0]), z1b = unpack2(acc1[i][1]);
        const float2 z3a = unpack2(acc3[i][0]), z3b = unpack2(acc3[i][1]);
        float4 o;
        o.x = silu_f(z1a.x) * z3a.x;
        o.y = silu_f(z1a.y) * z3a.y;
        o.z = silu_f(z1b.x) * z3b.x;
        o.w = silu_f(z1b.y) * z3b.y;
        *(float4*)&g_hs[(size_t)(m0 + ty * 8 + i) * HSH + n0 + tx * 4] = o;
    }
}

// ---------------- routed FFN1: g_h = silu(Xg@w1[e]) * (Xg@w3[e]) ----------------
__global__ __launch_bounds__(256) void k_effn1(const float* __restrict__ X,
                                               const float* __restrict__ W1,
                                               const float* __restrict__ W3) {
    const int e = blockIdx.z;
    const int cnt = min(g_cnt[e], CAP);
    const int m0 = blockIdx.x * 128;
    if (m0 >= cnt) return;
    const int n0 = blockIdx.y * 64;

    __shared__ __align__(16) float As [16][128];
    __shared__ __align__(16) float Bs1[16][64];
    __shared__ __align__(16) float Bs3[16][64];
    const int tid = threadIdx.x;
    const int ar = tid >> 1, ac = (tid & 1) * 8;
    const int br = tid >> 4, bc = (tid & 15) * 4;
    const int ty = tid >> 4, tx = tid & 15;

    const int myrow = m0 + ar;
    const int tok = (myrow < cnt) ? g_tok[e * CAP + myrow] : -1;
    const float* W1g = W1 + (size_t)e * DMODEL * HEXP;
    const float* W3g = W3 + (size_t)e * DMODEL * HEXP;

    u64 acc1[8][2], acc3[8][2];
    #pragma unroll
    for (int i = 0; i < 8; ++i) {
        acc1[i][0] = 0ULL; acc1[i][1] = 0ULL;
        acc3[i][0] = 0ULL; acc3[i][1] = 0ULL;
    }

    for (int k0 = 0; k0 < DMODEL; k0 += 16) {
        float4 a0 = make_float4(0.f, 0.f, 0.f, 0.f);
        float4 a1 = make_float4(0.f, 0.f, 0.f, 0.f);
        if (tok >= 0) {
            a0 = *(const float4*)(X + (size_t)tok * DMODEL + k0 + ac);
            a1 = *(const float4*)(X + (size_t)tok * DMODEL + k0 + ac + 4);
        }
        As[ac + 0][ar] = a0.x; As[ac + 1][ar] = a0.y; As[ac + 2][ar] = a0.z; As[ac + 3][ar] = a0.w;
        As[ac + 4][ar] = a1.x; As[ac + 5][ar] = a1.y; As[ac + 6][ar] = a1.z; As[ac + 7][ar] = a1.w;
        *(float4*)&Bs1[br][bc] = *(const float4*)(W1g + (size_t)(k0 + br) * HEXP + n0 + bc);
        *(float4*)&Bs3[br][bc] = *(const float4*)(W3g + (size_t)(k0 + br) * HEXP + n0 + bc);
        __syncthreads();
        #pragma unroll
        for (int k = 0; k < 16; ++k) {
            const float4 av0 = *(const float4*)&As[k][ty * 8];
            const float4 av1 = *(const float4*)&As[k][ty * 8 + 4];
            u64 ap[8];
            ap[0] = bcast2(av0.x); ap[1] = bcast2(av0.y); ap[2] = bcast2(av0.z); ap[3] = bcast2(av0.w);
            ap[4] = bcast2(av1.x); ap[5] = bcast2(av1.y); ap[6] = bcast2(av1.z); ap[7] = bcast2(av1.w);
            const ulonglong2 b1 = *(const ulonglong2*)&Bs1[k][tx * 4];
            const ulonglong2 b3 = *(const ulonglong2*)&Bs3[k][tx * 4];
            #pragma unroll
            for (int i = 0; i < 8; ++i) {
                fma2(acc1[i][0], ap[i], b1.x);
                fma2(acc1[i][1], ap[i], b1.y);
                fma2(acc3[i][0], ap[i], b3.x);
                fma2(acc3[i][1], ap[i], b3.y);
            }
        }
        __syncthreads();
    }
    #pragma unroll
    for (int i = 0; i < 8; ++i) {
        const int r = m0 + ty * 8 + i;
        if (r < cnt) {
            const float2 z1a = unpack2(acc1[i][0]), z1b = unpack2(acc1[i][1]);
            const float2 z3a = unpack2(acc3[i][0]), z3b = unpack2(acc3[i][1]);
            float4 o;
            o.x = silu_f(z1a.x) * z3a.x;
            o.y = silu_f(z1a.y) * z3a.y;
            o.z = silu_f(z1b.x) * z3b.x;
            o.w = silu_f(z1b.y) * z3b.y;
            *(float4*)&g_h[((size_t)e * CAP + r) * HEXP + n0 + tx * 4] = o;
        }
    }
}

// ================================================================================
// Single-operand GEMM (FFN2), FFMA2 path.
// Tile: 128 x 128, BK=16, 256 threads, microtile 8x8 per thread.
// ================================================================================

// ---------------- shared expert FFN2: out = g_hs @ sw2 -------------------------
__global__ __launch_bounds__(256) void k_sffn2(const float* __restrict__ W2g,
                                               float* __restrict__ out) {
    __shared__ __align__(16) float As[16][128];
    __shared__ __align__(16) float Bs[16][128];
    const int tid = threadIdx.x;
    const int m0 = blockIdx.x * 128, n0 = blockIdx.y * 128;
    const int ar = tid >> 1, ac = (tid & 1) * 8;
    const int br = tid >> 4, bc = (tid & 15) * 8;
    const int ty = tid >> 4, tx = tid & 15;

    u64 acc[8][4];
    #pragma unroll
    for (int i = 0; i < 8; ++i)
        #pragma unroll
        for (int j = 0; j < 4; ++j) acc[i][j] = 0ULL;

    for (int k0 = 0; k0 < HSH; k0 += 16) {
        const float4 a0 = *(const float4*)(&g_hs[(size_t)(m0 + ar) * HSH + k0 + ac]);
        const float4 a1 = *(const float4*)(&g_hs[(size_t)(m0 + ar) * HSH + k0 + ac + 4]);
        As[ac + 0][ar] = a0.x; As[ac + 1][ar] = a0.y; As[ac + 2][ar] = a0.z; As[ac + 3][ar] = a0.w;
        As[ac + 4][ar] = a1.x; As[ac + 5][ar] = a1.y; As[ac + 6][ar] = a1.z; As[ac + 7][ar] = a1.w;
        *(float4*)&Bs[br][bc]     = *(const float4*)(W2g + (size_t)(k0 + br) * DMODEL + n0 + bc);
        *(float4*)&Bs[br][bc + 4] = *(const float4*)(W2g + (size_t)(k0 + br) * DMODEL + n0 + bc + 4);
        __syncthreads();
        #pragma unroll
        for (int k = 0; k < 16; ++k) {
            const float4 av0 = *(const float4*)&As[k][ty * 8];
            const float4 av1 = *(const float4*)&As[k][ty * 8 + 4];
            u64 ap[8];
            ap[0] = bcast2(av0.x); ap[1] = bcast2(av0.y); ap[2] = bcast2(av0.z); ap[3] = bcast2(av0.w);
            ap[4] = bcast2(av1.x); ap[5] = bcast2(av1.y); ap[6] = bcast2(av1.z); ap[7] = bcast2(av1.w);
            const ulonglong2 b01 = *(const ulonglong2*)&Bs[k][tx * 8];
            const ulonglong2 b23 = *(const ulonglong2*)&Bs[k][tx * 8 + 4];
            #pragma unroll
            for (int i = 0; i < 8; ++i) {
                fma2(acc[i][0], ap[i], b01.x);
                fma2(acc[i][1], ap[i], b01.y);
                fma2(acc[i][2], ap[i], b23.x);
                fma2(acc[i][3], ap[i], b23.y);
            }
        }
        __syncthreads();
    }
    #pragma unroll
    for (int i = 0; i < 8; ++i) {
        const float2 v0 = unpack2(acc[i][0]), v1 = unpack2(acc[i][1]);
        const float2 v2 = unpack2(acc[i][2]), v3 = unpack2(acc[i][3]);
        float* orow = out + (size_t)(m0 + ty * 8 + i) * DMODEL + n0 + tx * 8;
        *(float4*)orow       = make_float4(v0.x, v0.y, v1.x, v1.y);
        *(float4*)(orow + 4) = make_float4(v2.x, v2.y, v3.x, v3.y);
    }
}

// ---------------- routed FFN2 + combine: out[t] += w * (g_h @ w2[e]) ------------
__global__ __launch_bounds__(256) void k_effn2(const float* __restrict__ W2,
                                               float* __restrict__ out) {
    const int e = blockIdx.z;
    const int cnt = min(g_cnt[e], CAP);
    const int m0 = blockIdx.x * 128;
    if (m0 >= cnt) return;
    const int n0 = blockIdx.y * 128;

    __shared__ __align__(16) float As[16][128];
    __shared__ __align__(16) float Bs[16][128];
    const int tid = threadIdx.x;
    const int ar = tid >> 1, ac = (tid & 1) * 8;
    const int br = tid >> 4, bc = (tid & 15) * 8;
    const int ty = tid >> 4, tx = tid & 15;

    const int arow = m0 + ar;
    const bool avalid = (arow < cnt);
    const float* W2g = W2 + (size_t)e * HEXP * DMODEL;

    u64 acc[8][4];
    #pragma unroll
    for (int i = 0; i < 8; ++i)
        #pragma unroll
        for (int j = 0; j < 4; ++j) acc[i][j] = 0ULL;

    for (int k0 = 0; k0 < HEXP; k0 += 16) {
        float4 a0 = make_float4(0.f, 0.f, 0.f, 0.f);
        float4 a1 = make_float4(0.f, 0.f, 0.f, 0.f);
        if (avalid) {
            a0 = *(const float4*)(&g_h[((size_t)e * CAP + arow) * HEXP + k0 + ac]);
            a1 = *(const float4*)(&g_h[((size_t)e * CAP + arow) * HEXP + k0 + ac + 4]);
        }
        As[ac + 0][ar] = a0.x; As[ac + 1][ar] = a0.y; As[ac + 2][ar] = a0.z; As[ac + 3][ar] = a0.w;
        As[ac + 4][ar] = a1.x; As[ac + 5][ar] = a1.y; As[ac + 6][ar] = a1.z; As[ac + 7][ar] = a1.w;
        *(float4*)&Bs[br][bc]     = *(const float4*)(W2g + (size_t)(k0 + br) * DMODEL + n0 + bc);
        *(float4*)&Bs[br][bc + 4] = *(const float4*)(W2g + (size_t)(k0 + br) * DMODEL + n0 + bc + 4);
        __syncthreads();
        #pragma unroll
        for (int k = 0; k < 16; ++k) {
            const float4 av0 = *(const float4*)&As[k][ty * 8];
            const float4 av1 = *(const float4*)&As[k][ty * 8 + 4];
            u64 ap[8];
            ap[0] = bcast2(av0.x); ap[1] = bcast2(av0.y); ap[2] = bcast2(av0.z); ap[3] = bcast2(av0.w);
            ap[4] = bcast2(av1.x); ap[5] = bcast2(av1.y); ap[6] = bcast2(av1.z); ap[7] = bcast2(av1.w);
            const ulonglong2 b01 = *(const ulonglong2*)&Bs[k][tx * 8];
            const ulonglong2 b23 = *(const ulonglong2*)&Bs[k][tx * 8 + 4];
            #pragma unroll
            for (int i = 0; i < 8; ++i) {
                fma2(acc[i][0], ap[i], b01.x);
                fma2(acc[i][1], ap[i], b01.y);
                fma2(acc[i][2], ap[i], b23.x);
                fma2(acc[i][3], ap[i], b23.y);
            }
        }
        __syncthreads();
    }
    #pragma unroll
    for (int i = 0; i < 8; ++i) {
        const int r = m0 + ty * 8 + i;
        if (r < cnt) {
            const int   t = g_tok[e * CAP + r];
            const float w = g_wgt[e * CAP + r];
            float* orow = out + (size_t)t * DMODEL + n0 + tx * 8;
            const float2 v0 = unpack2(acc[i][0]), v1 = unpack2(acc[i][1]);
            const float2 v2 = unpack2(acc[i][2]), v3 = unpack2(acc[i][3]);
            atomicAdd(orow + 0, w * v0.x);
            atomicAdd(orow + 1, w * v0.y);
            atomicAdd(orow + 2, w * v1.x);
            atomicAdd(orow + 3, w * v1.y);
            atomicAdd(orow + 4, w * v2.x);
            atomicAdd(orow + 5, w * v2.y);
            atomicAdd(orow + 6, w * v3.x);
            atomicAdd(orow + 7, w * v3.y);
        }
    }
}

// ---------------- launch ---------------------------------------------------------
extern "C" void kernel_launch(void* const* d_in, const int* in_sizes, int n_in,
                              void* d_out, int out_size) {
    const float* x    = (const float*)d_in[0];
    const float* gate = (const float*)d_in[1];
    const float* w1   = (const float*)d_in[2];
    const float* w3   = (const float*)d_in[3];
    const float* w2   = (const float*)d_in[4];
    const float* sw1  = (const float*)d_in[5];
    const float* sw3  = (const float*)d_in[6];
    const float* sw2  = (const float*)d_in[7];
    float* out = (float*)d_out;

    k_zero<<<1, 64>>>();
    k_router<<<NTOK / RTB, 128>>>(x, gate);
    k_sffn1<<<dim3(NTOK / 128, HSH / 64), 256>>>(x, sw1, sw3);
    k_sffn2<<<dim3(NTOK / 128, DMODEL / 128), 256>>>(sw2, out);
    k_effn1<<<dim3(CAP / 128, HEXP / 64, NEXP), 256>>>(x, w1, w3);
    k_effn2<<<dim3(CAP / 128, DMODEL / 128, NEXP), 256>>>(w2, out);
}

// round 5
// speedup vs baseline: 1.4251x; 1.4251x over previous
#include <cuda_runtime.h>
#include <stdint.h>

// Problem constants
#define NTOK   8192
#define DMODEL 512
#define NEXP   64
#define HEXP   256
#define HSH    512
#define CAP    1024
#define RSCALE 2.5f

// ---------------- scratch ------------------------------------------------------
__device__ int   g_cnt[NEXP];
__device__ int   g_tok[NEXP * CAP];
__device__ float g_wgt[NEXP * CAP];
__device__ float g_h [(size_t)NEXP * CAP * HEXP];
__device__ float g_hs[(size_t)NTOK * HSH];

// ---------------- helpers ------------------------------------------------------
__device__ __forceinline__ uint32_t bfbits(float x) {   // rn bf16, kept in high 16
    uint32_t u = __float_as_uint(x);
    return (u + 0x7FFFu + ((u >> 16) & 1u)) & 0xFFFF0000u;
}
__device__ __forceinline__ float bfres(float x) {       // residual after bf16 round
    return x - __uint_as_float(bfbits(x));
}
__device__ __forceinline__ uint32_t packbf(float e, float o) {  // e->low half, o->high half
    return bfbits(o) | (bfbits(e) >> 16);
}
__device__ __forceinline__ float silu_f(float z) { return z / (1.f + __expf(-z)); }

__device__ __forceinline__ void mma16816(float c[4], const uint32_t a[4],
                                         uint32_t b0, uint32_t b1) {
    asm volatile(
        "mma.sync.aligned.m16n8k16.row.col.f32.bf16.bf16.f32 "
        "{%0,%1,%2,%3}, {%4,%5,%6,%7}, {%8,%9}, {%0,%1,%2,%3};"
        : "+f"(c[0]), "+f"(c[1]), "+f"(c[2]), "+f"(c[3])
        : "r"(a[0]), "r"(a[1]), "r"(a[2]), "r"(a[3]), "r"(b0), "r"(b1));
}

// ---------------- k0: zero counters --------------------------------------------
__global__ void k_zero() {
    if (threadIdx.x < NEXP) g_cnt[threadIdx.x] = 0;
}

// ---------------- k1: router + dispatch (unchanged, proven) --------------------
#define RTB 16
__global__ void k_router(const float* __restrict__ x, const float* __restrict__ gw) {
    __shared__ __align__(16) float xs[RTB][DMODEL];
    __shared__ float sc[RTB][NEXP];
    const int tid = threadIdx.x;
    const int t0  = blockIdx.x * RTB;

    const float4* src = (const float4*)(x + (size_t)t0 * DMODEL);
    float4* dst = (float4*)&xs[0][0];
    #pragma unroll
    for (int i = tid; i < RTB * DMODEL / 4; i += 128) dst[i] = src[i];
    __syncthreads();

    const int e    = tid & 63;
    const int half = tid >> 6;
    const float* g = gw + (size_t)e * DMODEL;

    float acc[8];
    #pragma unroll
    for (int j = 0; j < 8; ++j) acc[j] = 0.f;
    for (int d = 0; d < DMODEL; d += 4) {
        const float4 gv = *(const float4*)(g + d);
        #pragma unroll
        for (int j = 0; j < 8; ++j) {
            const int tt = half * 8 + j;
            acc[j] = fmaf(gv.x, xs[tt][d],     acc[j]);
            acc[j] = fmaf(gv.y, xs[tt][d + 1], acc[j]);
            acc[j] = fmaf(gv.z, xs[tt][d + 2], acc[j]);
            acc[j] = fmaf(gv.w, xs[tt][d + 3], acc[j]);
        }
    }
    #pragma unroll
    for (int j = 0; j < 8; ++j)
        sc[half * 8 + j][e] = 1.f / (1.f + __expf(-acc[j]));
    __syncthreads();

    if (tid < RTB) {
        const int t = t0 + tid;
        float s0 = -1.f, s1 = -1.f; int e0 = 0, e1 = 0;
        #pragma unroll 8
        for (int i = 0; i < NEXP; ++i) {
            const float s = sc[tid][i];
            if (s > s0)      { s1 = s0; e1 = e0; s0 = s; e0 = i; }
            else if (s > s1) { s1 = s;  e1 = i; }
        }
        const float inv = RSCALE / (s0 + s1 + 1e-20f);
        int p0 = atomicAdd(&g_cnt[e0], 1);
        if (p0 < CAP) { g_tok[e0 * CAP + p0] = t; g_wgt[e0 * CAP + p0] = s0 * inv; }
        int p1 = atomicAdd(&g_cnt[e1], 1);
        if (p1 < CAP) { g_tok[e1 * CAP + p1] = t; g_wgt[e1 * CAP + p1] = s1 * inv; }
    }
}

// ================================================================================
// bf16x3 split mma.sync GEMMs.
// BK=32 (2 k16 steps). smem: A as [16 kpairs][128 m] bf16x2, B as [16 kpairs][N n].
// 8 warps: wm = (w>>2)*64, warp covers 4 m-frags of 16.
// ================================================================================

// ---- FFN1 body (dual B, SwiGLU epilogue) shared by sffn1 / effn1 ---------------
// A-loader and epilogue differ -> two kernels with duplicated structure.

// shared FFN1: g_hs = silu(X@sw1)*(X@sw3); K=DMODEL, B [K][HSH]
__global__ __launch_bounds__(256) void k_sffn1(const float* __restrict__ X,
                                               const float* __restrict__ B1,
                                               const float* __restrict__ B3) {
    __shared__ uint32_t Ah[16][132], Al[16][132];
    __shared__ uint32_t B1h[16][68], B1l[16][68], B3h[16][68], B3l[16][68];
    const int tid = threadIdx.x, w = tid >> 5, lane = tid & 31;
    const int gid = lane >> 2, tig = lane & 3;
    const int m0 = blockIdx.x * 128, n0 = blockIdx.y * 64;
    const int wm = (w >> 2) * 64, wn = (w & 3) * 16;

    float acc1[4][2][4], acc3[4][2][4];
    #pragma unroll
    for (int mf = 0; mf < 4; ++mf)
        #pragma unroll
        for (int nf = 0; nf < 2; ++nf)
            #pragma unroll
            for (int q = 0; q < 4; ++q) { acc1[mf][nf][q] = 0.f; acc3[mf][nf][q] = 0.f; }

    for (int k0 = 0; k0 < DMODEL; k0 += 32) {
        // A tile: 128 x 32
        #pragma unroll
        for (int it = 0; it < 4; ++it) {
            const int idx = it * 256 + tid;
            const int row = idx >> 3, kq = idx & 7;
            const float4 v = *(const float4*)(X + (size_t)(m0 + row) * DMODEL + k0 + kq * 4);
            Ah[kq * 2 + 0][row] = packbf(v.x, v.y);
            Ah[kq * 2 + 1][row] = packbf(v.z, v.w);
            Al[kq * 2 + 0][row] = packbf(bfres(v.x), bfres(v.y));
            Al[kq * 2 + 1][row] = packbf(bfres(v.z), bfres(v.w));
        }
        // B tiles: 32 x 64 each; 16 kpairs x 16 nquads = 256 tasks
        {
            const int kp = tid >> 4, nq = tid & 15;
            const float* p1e = B1 + (size_t)(k0 + kp * 2) * HSH + n0 + nq * 4;
            const float4 ue = *(const float4*)p1e;
            const float4 uo = *(const float4*)(p1e + HSH);
            *(uint4*)&B1h[kp][nq * 4] = make_uint4(packbf(ue.x, uo.x), packbf(ue.y, uo.y),
                                                   packbf(ue.z, uo.z), packbf(ue.w, uo.w));
            *(uint4*)&B1l[kp][nq * 4] = make_uint4(packbf(bfres(ue.x), bfres(uo.x)),
                                                   packbf(bfres(ue.y), bfres(uo.y)),
                                                   packbf(bfres(ue.z), bfres(uo.z)),
                                                   packbf(bfres(ue.w), bfres(uo.w)));
            const float* p3e = B3 + (size_t)(k0 + kp * 2) * HSH + n0 + nq * 4;
            const float4 ve = *(const float4*)p3e;
            const float4 vo = *(const float4*)(p3e + HSH);
            *(uint4*)&B3h[kp][nq * 4] = make_uint4(packbf(ve.x, vo.x), packbf(ve.y, vo.y),
                                                   packbf(ve.z, vo.z), packbf(ve.w, vo.w));
            *(uint4*)&B3l[kp][nq * 4] = make_uint4(packbf(bfres(ve.x), bfres(vo.x)),
                                                   packbf(bfres(ve.y), bfres(vo.y)),
                                                   packbf(bfres(ve.z), bfres(vo.z)),
                                                   packbf(bfres(ve.w), bfres(vo.w)));
        }
        __syncthreads();
        #pragma unroll
        for (int ks = 0; ks < 2; ++ks) {
            const int kb = ks * 8;
            uint32_t ah[4][4], al[4][4];
            #pragma unroll
            for (int mf = 0; mf < 4; ++mf) {
                const int m = wm + mf * 16 + gid;
                ah[mf][0] = Ah[kb + tig][m];     ah[mf][1] = Ah[kb + tig][m + 8];
                ah[mf][2] = Ah[kb + tig + 4][m]; ah[mf][3] = Ah[kb + tig + 4][m + 8];
                al[mf][0] = Al[kb + tig][m];     al[mf][1] = Al[kb + tig][m + 8];
                al[mf][2] = Al[kb + tig + 4][m]; al[mf][3] = Al[kb + tig + 4][m + 8];
            }
            #pragma unroll
            for (int nf = 0; nf < 2; ++nf) {
                const int n = wn + nf * 8 + gid;
                uint32_t b0, b1, c0, c1;
                b0 = B1h[kb + tig][n]; b1 = B1h[kb + tig + 4][n];
                c0 = B1l[kb + tig][n]; c1 = B1l[kb + tig + 4][n];
                #pragma unroll
                for (int mf = 0; mf < 4; ++mf) {
                    mma16816(acc1[mf][nf], ah[mf], b0, b1);
                    mma16816(acc1[mf][nf], al[mf], b0, b1);
                    mma16816(acc1[mf][nf], ah[mf], c0, c1);
                }
                b0 = B3h[kb + tig][n]; b1 = B3h[kb + tig + 4][n];
                c0 = B3l[kb + tig][n]; c1 = B3l[kb + tig + 4][n];
                #pragma unroll
                for (int mf = 0; mf < 4; ++mf) {
                    mma16816(acc3[mf][nf], ah[mf], b0, b1);
                    mma16816(acc3[mf][nf], al[mf], b0, b1);
                    mma16816(acc3[mf][nf], ah[mf], c0, c1);
                }
            }
        }
        __syncthreads();
    }
    #pragma unroll
    for (int mf = 0; mf < 4; ++mf)
        #pragma unroll
        for (int nf = 0; nf < 2; ++nf) {
            const int r0 = m0 + wm + mf * 16 + gid;
            const int c0 = n0 + wn + nf * 8 + tig * 2;
            float2 o;
            o.x = silu_f(acc1[mf][nf][0]) * acc3[mf][nf][0];
            o.y = silu_f(acc1[mf][nf][1]) * acc3[mf][nf][1];
            *(float2*)&g_hs[(size_t)r0 * HSH + c0] = o;
            o.x = silu_f(acc1[mf][nf][2]) * acc3[mf][nf][2];
            o.y = silu_f(acc1[mf][nf][3]) * acc3[mf][nf][3];
            *(float2*)&g_hs[(size_t)(r0 + 8) * HSH + c0] = o;
        }
}

// routed FFN1: g_h = silu(Xg@w1[e])*(Xg@w3[e]); gathered A rows
__global__ __launch_bounds__(256) void k_effn1(const float* __restrict__ X,
                                               const float* __restrict__ W1,
                                               const float* __restrict__ W3) {
    const int e = blockIdx.z;
    const int cnt = min(g_cnt[e], CAP);
    const int m0 = blockIdx.x * 128;
    if (m0 >= cnt) return;
    const int n0 = blockIdx.y * 64;
    const float* B1 = W1 + (size_t)e * DMODEL * HEXP;
    const float* B3 = W3 + (size_t)e * DMODEL * HEXP;

    __shared__ uint32_t Ah[16][132], Al[16][132];
    __shared__ uint32_t B1h[16][68], B1l[16][68], B3h[16][68], B3l[16][68];
    const int tid = threadIdx.x, w = tid >> 5, lane = tid & 31;
    const int gid = lane >> 2, tig = lane & 3;
    const int wm = (w >> 2) * 64, wn = (w & 3) * 16;

    float acc1[4][2][4], acc3[4][2][4];
    #pragma unroll
    for (int mf = 0; mf < 4; ++mf)
        #pragma unroll
        for (int nf = 0; nf < 2; ++nf)
            #pragma unroll
            for (int q = 0; q < 4; ++q) { acc1[mf][nf][q] = 0.f; acc3[mf][nf][q] = 0.f; }

    for (int k0 = 0; k0 < DMODEL; k0 += 32) {
        #pragma unroll
        for (int it = 0; it < 4; ++it) {
            const int idx = it * 256 + tid;
            const int row = idx >> 3, kq = idx & 7;
            float4 v = make_float4(0.f, 0.f, 0.f, 0.f);
            if (m0 + row < cnt) {
                const int tok = g_tok[e * CAP + m0 + row];
                v = *(const float4*)(X + (size_t)tok * DMODEL + k0 + kq * 4);
            }
            Ah[kq * 2 + 0][row] = packbf(v.x, v.y);
            Ah[kq * 2 + 1][row] = packbf(v.z, v.w);
            Al[kq * 2 + 0][row] = packbf(bfres(v.x), bfres(v.y));
            Al[kq * 2 + 1][row] = packbf(bfres(v.z), bfres(v.w));
        }
        {
            const int kp = tid >> 4, nq = tid & 15;
            const float* p1e = B1 + (size_t)(k0 + kp * 2) * HEXP + n0 + nq * 4;
            const float4 ue = *(const float4*)p1e;
            const float4 uo = *(const float4*)(p1e + HEXP);
            *(uint4*)&B1h[kp][nq * 4] = make_uint4(packbf(ue.x, uo.x), packbf(ue.y, uo.y),
                                                   packbf(ue.z, uo.z), packbf(ue.w, uo.w));
            *(uint4*)&B1l[kp][nq * 4] = make_uint4(packbf(bfres(ue.x), bfres(uo.x)),
                                                   packbf(bfres(ue.y), bfres(uo.y)),
                                                   packbf(bfres(ue.z), bfres(uo.z)),
                                                   packbf(bfres(ue.w), bfres(uo.w)));
            const float* p3e = B3 + (size_t)(k0 + kp * 2) * HEXP + n0 + nq * 4;
            const float4 ve = *(const float4*)p3e;
            const float4 vo = *(const float4*)(p3e + HEXP);
            *(uint4*)&B3h[kp][nq * 4] = make_uint4(packbf(ve.x, vo.x), packbf(ve.y, vo.y),
                                                   packbf(ve.z, vo.z), packbf(ve.w, vo.w));
            *(uint4*)&B3l[kp][nq * 4] = make_uint4(packbf(bfres(ve.x), bfres(vo.x)),
                                                   packbf(bfres(ve.y), bfres(vo.y)),
                                                   packbf(bfres(ve.z), bfres(vo.z)),
                                                   packbf(bfres(ve.w), bfres(vo.w)));
        }
        __syncthreads();
        #pragma unroll
        for (int ks = 0; ks < 2; ++ks) {
            const int kb = ks * 8;
            uint32_t ah[4][4], al[4][4];
            #pragma unroll
            for (int mf = 0; mf < 4; ++mf) {
                const int m = wm + mf * 16 + gid;
                ah[mf][0] = Ah[kb + tig][m];     ah[mf][1] = Ah[kb + tig][m + 8];
                ah[mf][2] = Ah[kb + tig + 4][m]; ah[mf][3] = Ah[kb + tig + 4][m + 8];
                al[mf][0] = Al[kb + tig][m];     al[mf][1] = Al[kb + tig][m + 8];
                al[mf][2] = Al[kb + tig + 4][m]; al[mf][3] = Al[kb + tig + 4][m + 8];
            }
            #pragma unroll
            for (int nf = 0; nf < 2; ++nf) {
                const int n = wn + nf * 8 + gid;
                uint32_t b0, b1, c0, c1;
                b0 = B1h[kb + tig][n]; b1 = B1h[kb + tig + 4][n];
                c0 = B1l[kb + tig][n]; c1 = B1l[kb + tig + 4][n];
                #pragma unroll
                for (int mf = 0; mf < 4; ++mf) {
                    mma16816(acc1[mf][nf], ah[mf], b0, b1);
                    mma16816(acc1[mf][nf], al[mf], b0, b1);
                    mma16816(acc1[mf][nf], ah[mf], c0, c1);
                }
                b0 = B3h[kb + tig][n]; b1 = B3h[kb + tig + 4][n];
                c0 = B3l[kb + tig][n]; c1 = B3l[kb + tig + 4][n];
                #pragma unroll
                for (int mf = 0; mf < 4; ++mf) {
                    mma16816(acc3[mf][nf], ah[mf], b0, b1);
                    mma16816(acc3[mf][nf], al[mf], b0, b1);
                    mma16816(acc3[mf][nf], ah[mf], c0, c1);
                }
            }
        }
        __syncthreads();
    }
    #pragma unroll
    for (int mf = 0; mf < 4; ++mf)
        #pragma unroll
        for (int nf = 0; nf < 2; ++nf) {
            const int r0 = m0 + wm + mf * 16 + gid;
            const int c0 = n0 + wn + nf * 8 + tig * 2;
            if (r0 < cnt) {
                float2 o;
                o.x = silu_f(acc1[mf][nf][0]) * acc3[mf][nf][0];
                o.y = silu_f(acc1[mf][nf][1]) * acc3[mf][nf][1];
                *(float2*)&g_h[((size_t)e * CAP + r0) * HEXP + c0] = o;
            }
            if (r0 + 8 < cnt) {
                float2 o;
                o.x = silu_f(acc1[mf][nf][2]) * acc3[mf][nf][2];
                o.y = silu_f(acc1[mf][nf][3]) * acc3[mf][nf][3];
                *(float2*)&g_h[((size_t)e * CAP + r0 + 8) * HEXP + c0] = o;
            }
        }
}

// shared FFN2: out = g_hs @ sw2; K=HSH, B [K][DMODEL], N tile 128
__global__ __launch_bounds__(256) void k_sffn2(const float* __restrict__ B2,
                                               float* __restrict__ out) {
    __shared__ uint32_t Ah[16][132], Al[16][132], Bh[16][132], Bl[16][132];
    const int tid = threadIdx.x, w = tid >> 5, lane = tid & 31;
    const int gid = lane >> 2, tig = lane & 3;
    const int m0 = blockIdx.x * 128, n0 = blockIdx.y * 128;
    const int wm = (w >> 2) * 64, wn = (w & 3) * 32;

    float acc[4][4][4];
    #pragma unroll
    for (int mf = 0; mf < 4; ++mf)
        #pragma unroll
        for (int nf = 0; nf < 4; ++nf)
            #pragma unroll
            for (int q = 0; q < 4; ++q) acc[mf][nf][q] = 0.f;

    for (int k0 = 0; k0 < HSH; k0 += 32) {
        #pragma unroll
        for (int it = 0; it < 4; ++it) {
            const int idx = it * 256 + tid;
            const int row = idx >> 3, kq = idx & 7;
            const float4 v = *(const float4*)(g_hs + (size_t)(m0 + row) * HSH + k0 + kq * 4);
            Ah[kq * 2 + 0][row] = packbf(v.x, v.y);
            Ah[kq * 2 + 1][row] = packbf(v.z, v.w);
            Al[kq * 2 + 0][row] = packbf(bfres(v.x), bfres(v.y));
            Al[kq * 2 + 1][row] = packbf(bfres(v.z), bfres(v.w));
        }
        #pragma unroll
        for (int it = 0; it < 2; ++it) {
            const int idx = it * 256 + tid;
            const int kp = idx >> 5, nq = idx & 31;
            const float* pe = B2 + (size_t)(k0 + kp * 2) * DMODEL + n0 + nq * 4;
            const float4 ue = *(const float4*)pe;
            const float4 uo = *(const float4*)(pe + DMODEL);
            *(uint4*)&Bh[kp][nq * 4] = make_uint4(packbf(ue.x, uo.x), packbf(ue.y, uo.y),
                                                  packbf(ue.z, uo.z), packbf(ue.w, uo.w));
            *(uint4*)&Bl[kp][nq * 4] = make_uint4(packbf(bfres(ue.x), bfres(uo.x)),
                                                  packbf(bfres(ue.y), bfres(uo.y)),
                                                  packbf(bfres(ue.z), bfres(uo.z)),
                                                  packbf(bfres(ue.w), bfres(uo.w)));
        }
        __syncthreads();
        #pragma unroll
        for (int ks = 0; ks < 2; ++ks) {
            const int kb = ks * 8;
            uint32_t ah[4][4], al[4][4];
            #pragma unroll
            for (int mf = 0; mf < 4; ++mf) {
                const int m = wm + mf * 16 + gid;
                ah[mf][0] = Ah[kb + tig][m];     ah[mf][1] = Ah[kb + tig][m + 8];
                ah[mf][2] = Ah[kb + tig + 4][m]; ah[mf][3] = Ah[kb + tig + 4][m + 8];
                al[mf][0] = Al[kb + tig][m];     al[mf][1] = Al[kb + tig][m + 8];
                al[mf][2] = Al[kb + tig + 4][m]; al[mf][3] = Al[kb + tig + 4][m + 8];
            }
            #pragma unroll
            for (int nf = 0; nf < 4; ++nf) {
                const int n = wn + nf * 8 + gid;
                const uint32_t b0 = Bh[kb + tig][n], b1 = Bh[kb + tig + 4][n];
                const uint32_t c0 = Bl[kb + tig][n], c1 = Bl[kb + tig + 4][n];
                #pragma unroll
                for (int mf = 0; mf < 4; ++mf) {
                    mma16816(acc[mf][nf], ah[mf], b0, b1);
                    mma16816(acc[mf][nf], al[mf], b0, b1);
                    mma16816(acc[mf][nf], ah[mf], c0, c1);
                }
            }
        }
        __syncthreads();
    }
    #pragma unroll
    for (int mf = 0; mf < 4; ++mf)
        #pragma unroll
        for (int nf = 0; nf < 4; ++nf) {
            const int r0 = m0 + wm + mf * 16 + gid;
            const int c0 = n0 + wn + nf * 8 + tig * 2;
            *(float2*)&out[(size_t)r0 * DMODEL + c0] =
                make_float2(acc[mf][nf][0], acc[mf][nf][1]);
            *(float2*)&out[(size_t)(r0 + 8) * DMODEL + c0] =
                make_float2(acc[mf][nf][2], acc[mf][nf][3]);
        }
}

// routed FFN2 + combine: out[tok] += w * (g_h@w2[e]); K=HEXP
__global__ __launch_bounds__(256) void k_effn2(const float* __restrict__ W2,
                                               float* __restrict__ out) {
    const int e = blockIdx.z;
    const int cnt = min(g_cnt[e], CAP);
    const int m0 = blockIdx.x * 128;
    if (m0 >= cnt) return;
    const int n0 = blockIdx.y * 128;
    const float* B2 = W2 + (size_t)e * HEXP * DMODEL;

    __shared__ uint32_t Ah[16][132], Al[16][132], Bh[16][132], Bl[16][132];
    const int tid = threadIdx.x, w = tid >> 5, lane = tid & 31;
    const int gid = lane >> 2, tig = lane & 3;
    const int wm = (w >> 2) * 64, wn = (w & 3) * 32;

    float acc[4][4][4];
    #pragma unroll
    for (int mf = 0; mf < 4; ++mf)
        #pragma unroll
        for (int nf = 0; nf < 4; ++nf)
            #pragma unroll
            for (int q = 0; q < 4; ++q) acc[mf][nf][q] = 0.f;

    for (int k0 = 0; k0 < HEXP; k0 += 32) {
        #pragma unroll
        for (int it = 0; it < 4; ++it) {
            const int idx = it * 256 + tid;
            const int row = idx >> 3, kq = idx & 7;
            float4 v = make_float4(0.f, 0.f, 0.f, 0.f);
            if (m0 + row < cnt)
                v = *(const float4*)(g_h + ((size_t)e * CAP + m0 + row) * HEXP + k0 + kq * 4);
            Ah[kq * 2 + 0][row] = packbf(v.x, v.y);
            Ah[kq * 2 + 1][row] = packbf(v.z, v.w);
            Al[kq * 2 + 0][row] = packbf(bfres(v.x), bfres(v.y));
            Al[kq * 2 + 1][row] = packbf(bfres(v.z), bfres(v.w));
        }
        #pragma unroll
        for (int it = 0; it < 2; ++it) {
            const int idx = it * 256 + tid;
            const int kp = idx >> 5, nq = idx & 31;
            const float* pe = B2 + (size_t)(k0 + kp * 2) * DMODEL + n0 + nq * 4;
            const float4 ue = *(const float4*)pe;
            const float4 uo = *(const float4*)(pe + DMODEL);
            *(uint4*)&Bh[kp][nq * 4] = make_uint4(packbf(ue.x, uo.x), packbf(ue.y, uo.y),
                                                  packbf(ue.z, uo.z), packbf(ue.w, uo.w));
            *(uint4*)&Bl[kp][nq * 4] = make_uint4(packbf(bfres(ue.x), bfres(uo.x)),
                                                  packbf(bfres(ue.y), bfres(uo.y)),
                                                  packbf(bfres(ue.z), bfres(uo.z)),
                                                  packbf(bfres(ue.w), bfres(uo.w)));
        }
        __syncthreads();
        #pragma unroll
        for (int ks = 0; ks < 2; ++ks) {
            const int kb = ks * 8;
            uint32_t ah[4][4], al[4][4];
            #pragma unroll
            for (int mf = 0; mf < 4; ++mf) {
                const int m = wm + mf * 16 + gid;
                ah[mf][0] = Ah[kb + tig][m];     ah[mf][1] = Ah[kb + tig][m + 8];
                ah[mf][2] = Ah[kb + tig + 4][m]; ah[mf][3] = Ah[kb + tig + 4][m + 8];
                al[mf][0] = Al[kb + tig][m];     al[mf][1] = Al[kb + tig][m + 8];
                al[mf][2] = Al[kb + tig + 4][m]; al[mf][3] = Al[kb + tig + 4][m + 8];
            }
            #pragma unroll
            for (int nf = 0; nf < 4; ++nf) {
                const int n = wn + nf * 8 + gid;
                const uint32_t b0 = Bh[kb + tig][n], b1 = Bh[kb + tig + 4][n];
                const uint32_t c0 = Bl[kb + tig][n], c1 = Bl[kb + tig + 4][n];
                #pragma unroll
                for (int mf = 0; mf < 4; ++mf) {
                    mma16816(acc[mf][nf], ah[mf], b0, b1);
                    mma16816(acc[mf][nf], al[mf], b0, b1);
                    mma16816(acc[mf][nf], ah[mf], c0, c1);
                }
            }
        }
        __syncthreads();
    }
    #pragma unroll
    for (int mf = 0; mf < 4; ++mf) {
        const int r0 = m0 + wm + mf * 16 + gid;
        int   t0v = 0, t1v = 0;
        float w0 = 0.f, w1 = 0.f;
        const bool ok0 = (r0 < cnt), ok1 = (r0 + 8 < cnt);
        if (ok0) { t0v = g_tok[e * CAP + r0];     w0 = g_wgt[e * CAP + r0]; }
        if (ok1) { t1v = g_tok[e * CAP + r0 + 8]; w1 = g_wgt[e * CAP + r0 + 8]; }
        #pragma unroll
        for (int nf = 0; nf < 4; ++nf) {
            const int c0 = n0 + wn + nf * 8 + tig * 2;
            if (ok0) {
                atomicAdd(&out[(size_t)t0v * DMODEL + c0],     w0 * acc[mf][nf][0]);
                atomicAdd(&out[(size_t)t0v * DMODEL + c0 + 1], w0 * acc[mf][nf][1]);
            }
            if (ok1) {
                atomicAdd(&out[(size_t)t1v * DMODEL + c0],     w1 * acc[mf][nf][2]);
                atomicAdd(&out[(size_t)t1v * DMODEL + c0 + 1], w1 * acc[mf][nf][3]);
            }
        }
    }
}

// ---------------- launch ---------------------------------------------------------
extern "C" void kernel_launch(void* const* d_in, const int* in_sizes, int n_in,
                              void* d_out, int out_size) {
    const float* x    = (const float*)d_in[0];
    const float* gate = (const float*)d_in[1];
    const float* w1   = (const float*)d_in[2];
    const float* w3   = (const float*)d_in[3];
    const float* w2   = (const float*)d_in[4];
    const float* sw1  = (const float*)d_in[5];
    const float* sw3  = (const float*)d_in[6];
    const float* sw2  = (const float*)d_in[7];
    float* out = (float*)d_out;

    k_zero<<<1, 64>>>();
    k_router<<<NTOK / RTB, 128>>>(x, gate);
    k_sffn1<<<dim3(NTOK / 128, HSH / 64), 256>>>(x, sw1, sw3);
    k_effn1<<<dim3(CAP / 128, HEXP / 64, NEXP), 256>>>(x, w1, w3);
    k_sffn2<<<dim3(NTOK / 128, DMODEL / 128), 256>>>(sw2, out);
    k_effn2<<<dim3(CAP / 128, DMODEL / 128, NEXP), 256>>>(w2, out);
}

// round 6
// speedup vs baseline: 3.2194x; 2.2590x over previous
#include <cuda_runtime.h>
#include <stdint.h>

#define NTOK   8192
#define DMODEL 512
#define NEXP   64
#define HEXP   256
#define HSH    512
#define CAP    1024
#define RSCALE 2.5f

typedef unsigned short u16;
typedef unsigned int   u32;

// ---------------- scratch ------------------------------------------------------
__device__ int   g_cnt[NEXP];
__device__ int   g_tok[NEXP * CAP];
__device__ float g_wgt[NEXP * CAP];

// preconverted bf16 hi/lo operands
__device__ u16 g_xh[(size_t)NTOK * DMODEL],  g_xl[(size_t)NTOK * DMODEL];
__device__ u16 g_w1h[(size_t)NEXP * DMODEL * HEXP], g_w1l[(size_t)NEXP * DMODEL * HEXP];
__device__ u16 g_w3h[(size_t)NEXP * DMODEL * HEXP], g_w3l[(size_t)NEXP * DMODEL * HEXP];
__device__ u16 g_w2h[(size_t)NEXP * HEXP * DMODEL], g_w2l[(size_t)NEXP * HEXP * DMODEL];
__device__ u16 g_s1h[DMODEL * HSH], g_s1l[DMODEL * HSH];
__device__ u16 g_s3h[DMODEL * HSH], g_s3l[DMODEL * HSH];
__device__ u16 g_s2h[HSH * DMODEL], g_s2l[HSH * DMODEL];
// intermediates (bf16 hi/lo)
__device__ u16 g_hh[(size_t)NEXP * CAP * HEXP], g_hl[(size_t)NEXP * CAP * HEXP];
__device__ u16 g_hsh[(size_t)NTOK * HSH],       g_hsl[(size_t)NTOK * HSH];

// ---------------- helpers ------------------------------------------------------
__device__ __forceinline__ u16 bf16h(float x) {
    uint32_t u = __float_as_uint(x);
    u += 0x7FFFu + ((u >> 16) & 1u);
    return (u16)(u >> 16);
}
__device__ __forceinline__ float bf2f(u16 h) { return __uint_as_float(((uint32_t)h) << 16); }
__device__ __forceinline__ float silu_f(float z) { return z / (1.f + __expf(-z)); }

__device__ __forceinline__ void mma16816(float c[4], const u32 a[4], u32 b0, u32 b1) {
    asm volatile(
        "mma.sync.aligned.m16n8k16.row.col.f32.bf16.bf16.f32 "
        "{%0,%1,%2,%3}, {%4,%5,%6,%7}, {%8,%9}, {%0,%1,%2,%3};"
        : "+f"(c[0]), "+f"(c[1]), "+f"(c[2]), "+f"(c[3])
        : "r"(a[0]), "r"(a[1]), "r"(a[2]), "r"(a[3]), "r"(b0), "r"(b1));
}
__device__ __forceinline__ void ldm_x4(u32 r[4], u32 a) {
    asm volatile("ldmatrix.sync.aligned.m8n8.x4.shared.b16 {%0,%1,%2,%3}, [%4];"
                 : "=r"(r[0]), "=r"(r[1]), "=r"(r[2]), "=r"(r[3]) : "r"(a));
}
__device__ __forceinline__ void ldm_x4t(u32 r[4], u32 a) {
    asm volatile("ldmatrix.sync.aligned.m8n8.x4.trans.shared.b16 {%0,%1,%2,%3}, [%4];"
                 : "=r"(r[0]), "=r"(r[1]), "=r"(r[2]), "=r"(r[3]) : "r"(a));
}
__device__ __forceinline__ void cpa16(u32 d, const void* s) {
    asm volatile("cp.async.ca.shared.global [%0], [%1], 16;" :: "r"(d), "l"(s));
}
__device__ __forceinline__ void cpa16z(u32 d, const void* s, int sz) {
    asm volatile("cp.async.ca.shared.global [%0], [%1], 16, %2;" :: "r"(d), "l"(s), "r"(sz));
}
#define CPCOMMIT() asm volatile("cp.async.commit_group;" ::: "memory")
#define CPWAIT(n)  asm volatile("cp.async.wait_group %0;" :: "n"(n) : "memory")

// smem layouts (bytes)
#define OAH   0
#define OAL   10240
#define OB1H  20480
#define OB1L  25088
#define OB3H  29696
#define OB3L  34304
#define S1STG 38912            // FFN1 stage (A 2x10240 + B 4x4608)
#define OBH   20480
#define OBL   29184
#define S2STG 37888            // FFN2 stage (A 2x10240 + B 2x8704)

// ---------------- k0 / router --------------------------------------------------
__global__ void k_zero() { if (threadIdx.x < NEXP) g_cnt[threadIdx.x] = 0; }

#define RTB 16
__global__ void k_router(const float* __restrict__ x, const float* __restrict__ gw) {
    __shared__ __align__(16) float xs[RTB][DMODEL];
    __shared__ float sc[RTB][NEXP];
    const int tid = threadIdx.x;
    const int t0  = blockIdx.x * RTB;
    const float4* src = (const float4*)(x + (size_t)t0 * DMODEL);
    float4* dst = (float4*)&xs[0][0];
    #pragma unroll
    for (int i = tid; i < RTB * DMODEL / 4; i += 128) dst[i] = src[i];
    __syncthreads();

    const int e = tid & 63, half = tid >> 6;
    const float* g = gw + (size_t)e * DMODEL;
    float acc[8];
    #pragma unroll
    for (int j = 0; j < 8; ++j) acc[j] = 0.f;
    for (int d = 0; d < DMODEL; d += 4) {
        const float4 gv = *(const float4*)(g + d);
        #pragma unroll
        for (int j = 0; j < 8; ++j) {
            const int tt = half * 8 + j;
            acc[j] = fmaf(gv.x, xs[tt][d],     acc[j]);
            acc[j] = fmaf(gv.y, xs[tt][d + 1], acc[j]);
            acc[j] = fmaf(gv.z, xs[tt][d + 2], acc[j]);
            acc[j] = fmaf(gv.w, xs[tt][d + 3], acc[j]);
        }
    }
    #pragma unroll
    for (int j = 0; j < 8; ++j)
        sc[half * 8 + j][e] = 1.f / (1.f + __expf(-acc[j]));
    __syncthreads();

    if (tid < RTB) {
        const int t = t0 + tid;
        float s0 = -1.f, s1 = -1.f; int e0 = 0, e1 = 0;
        #pragma unroll 8
        for (int i = 0; i < NEXP; ++i) {
            const float s = sc[tid][i];
            if (s > s0)      { s1 = s0; e1 = e0; s0 = s; e0 = i; }
            else if (s > s1) { s1 = s;  e1 = i; }
        }
        const float inv = RSCALE / (s0 + s1 + 1e-20f);
        int p0 = atomicAdd(&g_cnt[e0], 1);
        if (p0 < CAP) { g_tok[e0 * CAP + p0] = t; g_wgt[e0 * CAP + p0] = s0 * inv; }
        int p1 = atomicAdd(&g_cnt[e1], 1);
        if (p1 < CAP) { g_tok[e1 * CAP + p1] = t; g_wgt[e1 * CAP + p1] = s1 * inv; }
    }
}

// ---------------- preconvert fp32 -> bf16 hi/lo --------------------------------
__global__ void k_cvt(const float* __restrict__ s, u16* __restrict__ dh,
                      u16* __restrict__ dl, int n) {
    const int i = (blockIdx.x * blockDim.x + threadIdx.x) * 8;
    if (i >= n) return;
    const float4 v0 = *(const float4*)(s + i);
    const float4 v1 = *(const float4*)(s + i + 4);
    const float vv[8] = {v0.x, v0.y, v0.z, v0.w, v1.x, v1.y, v1.z, v1.w};
    u16 h[8], l[8];
    #pragma unroll
    for (int j = 0; j < 8; ++j) {
        h[j] = bf16h(vv[j]);
        l[j] = bf16h(vv[j] - bf2f(h[j]));
    }
    uint4 ph, pl;
    ph.x = h[0] | ((u32)h[1] << 16); ph.y = h[2] | ((u32)h[3] << 16);
    ph.z = h[4] | ((u32)h[5] << 16); ph.w = h[6] | ((u32)h[7] << 16);
    pl.x = l[0] | ((u32)l[1] << 16); pl.y = l[2] | ((u32)l[3] << 16);
    pl.z = l[4] | ((u32)l[5] << 16); pl.w = l[6] | ((u32)l[7] << 16);
    *(uint4*)(dh + i) = ph;
    *(uint4*)(dl + i) = pl;
}

// ---------------- FFN1 loaders / mma -------------------------------------------
__device__ __forceinline__ void ffn1_load(u32 bp, const u16* Ah, const u16* Al,
                                          const u16* B1h, const u16* B1l,
                                          const u16* B3h, const u16* B3l,
                                          int m0, int n0, int k0, int tid, int nstr) {
    #pragma unroll
    for (int r = 0; r < 2; ++r) {
        const int task = tid + r * 256;
        const int row = task >> 2, cq = task & 3;
        const size_t so = (size_t)(m0 + row) * DMODEL + k0 + cq * 8;
        const u32 d = bp + row * 80 + cq * 16;
        cpa16(d + OAH, Ah + so);
        cpa16(d + OAL, Al + so);
    }
    const int row = tid >> 3, cq = tid & 7;
    const size_t so = (size_t)(k0 + row) * nstr + n0 + cq * 8;
    const u32 d = bp + row * 144 + cq * 16;
    cpa16(d + OB1H, B1h + so);
    cpa16(d + OB1L, B1l + so);
    cpa16(d + OB3H, B3h + so);
    cpa16(d + OB3L, B3l + so);
}

__device__ __forceinline__ void ffn1_load_g(u32 bp, const u16* Ah, const u16* Al,
                                            const u16* B1h, const u16* B1l,
                                            const u16* B3h, const u16* B3l,
                                            int e, int cnt, int m0, int n0, int k0,
                                            int tid, int nstr) {
    #pragma unroll
    for (int r = 0; r < 2; ++r) {
        const int task = tid + r * 256;
        const int row = task >> 2, cq = task & 3;
        const int valid = (m0 + row < cnt);
        const int tok = valid ? g_tok[e * CAP + m0 + row] : 0;
        const size_t so = (size_t)tok * DMODEL + k0 + cq * 8;
        const int sz = valid ? 16 : 0;
        const u32 d = bp + row * 80 + cq * 16;
        cpa16z(d + OAH, Ah + so, sz);
        cpa16z(d + OAL, Al + so, sz);
    }
    const int row = tid >> 3, cq = tid & 7;
    const size_t so = (size_t)(k0 + row) * nstr + n0 + cq * 8;
    const u32 d = bp + row * 144 + cq * 16;
    cpa16(d + OB1H, B1h + so);
    cpa16(d + OB1L, B1l + so);
    cpa16(d + OB3H, B3h + so);
    cpa16(d + OB3L, B3l + so);
}

__device__ __forceinline__ void ffn1_mma(u32 bp, int wm, int wn, int lane,
                                         float acc1[4][2][4], float acc3[4][2][4]) {
    #pragma unroll
    for (int ks = 0; ks < 2; ++ks) {
        u32 ah[4][4], al[4][4];
        const int arow = lane & 15, acol = ks * 16 + ((lane >> 4) << 3);
        #pragma unroll
        for (int mf = 0; mf < 4; ++mf) {
            const u32 ap = bp + (wm + mf * 16 + arow) * 80 + acol * 2;
            ldm_x4(ah[mf], ap + OAH);
            ldm_x4(al[mf], ap + OAL);
        }
        const int mid = lane >> 3, rr = lane & 7;
        const int brow = ks * 16 + (mid & 1) * 8 + rr;
        const int bcol = wn + ((mid >> 1) << 3);
        const u32 bptr = bp + brow * 144 + bcol * 2;
        u32 b[4], c[4];
        ldm_x4t(b, bptr + OB1H);
        ldm_x4t(c, bptr + OB1L);
        #pragma unroll
        for (int mf = 0; mf < 4; ++mf)
            #pragma unroll
            for (int nf = 0; nf < 2; ++nf) {
                mma16816(acc1[mf][nf], ah[mf], b[nf * 2], b[nf * 2 + 1]);
                mma16816(acc1[mf][nf], al[mf], b[nf * 2], b[nf * 2 + 1]);
                mma16816(acc1[mf][nf], ah[mf], c[nf * 2], c[nf * 2 + 1]);
            }
        ldm_x4t(b, bptr + OB3H);
        ldm_x4t(c, bptr + OB3L);
        #pragma unroll
        for (int mf = 0; mf < 4; ++mf)
            #pragma unroll
            for (int nf = 0; nf < 2; ++nf) {
                mma16816(acc3[mf][nf], ah[mf], b[nf * 2], b[nf * 2 + 1]);
                mma16816(acc3[mf][nf], al[mf], b[nf * 2], b[nf * 2 + 1]);
                mma16816(acc3[mf][nf], ah[mf], c[nf * 2], c[nf * 2 + 1]);
            }
    }
}

// ---------------- FFN2 loaders / mma -------------------------------------------
__device__ __forceinline__ void ffn2_load(u32 bp, const u16* Ah, const u16* Al,
                                          const u16* Bh, const u16* Bl,
                                          int m0, int n0, int k0, int tid,
                                          int astr, int nstr) {
    #pragma unroll
    for (int r = 0; r < 2; ++r) {
        const int task = tid + r * 256;
        const int row = task >> 2, cq = task & 3;
        const size_t so = (size_t)(m0 + row) * astr + k0 + cq * 8;
        const u32 d = bp + row * 80 + cq * 16;
        cpa16(d + OAH, Ah + so);
        cpa16(d + OAL, Al + so);
    }
    #pragma unroll
    for (int r = 0; r < 2; ++r) {
        const int task = tid + r * 256;
        const int row = task >> 4, cq = task & 15;
        const size_t so = (size_t)(k0 + row) * nstr + n0 + cq * 8;
        const u32 d = bp + row * 272 + cq * 16;
        cpa16(d + OBH, Bh + so);
        cpa16(d + OBL, Bl + so);
    }
}

__device__ __forceinline__ void ffn2_load_g(u32 bp, const u16* Ah, const u16* Al,
                                            const u16* Bh, const u16* Bl,
                                            int e, int cnt, int m0, int n0, int k0,
                                            int tid, int nstr) {
    #pragma unroll
    for (int r = 0; r < 2; ++r) {
        const int task = tid + r * 256;
        const int row = task >> 2, cq = task & 3;
        const int valid = (m0 + row < cnt);
        const int sz = valid ? 16 : 0;
        const size_t so = ((size_t)e * CAP + m0 + row) * HEXP + k0 + cq * 8;
        const u32 d = bp + row * 80 + cq * 16;
        cpa16z(d + OAH, Ah + so, sz);
        cpa16z(d + OAL, Al + so, sz);
    }
    #pragma unroll
    for (int r = 0; r < 2; ++r) {
        const int task = tid + r * 256;
        const int row = task >> 4, cq = task & 15;
        const size_t so = (size_t)(k0 + row) * nstr + n0 + cq * 8;
        const u32 d = bp + row * 272 + cq * 16;
        cpa16(d + OBH, Bh + so);
        cpa16(d + OBL, Bl + so);
    }
}

__device__ __forceinline__ void ffn2_mma(u32 bp, int wm, int wn, int lane,
                                         float acc[4][4][4]) {
    #pragma unroll
    for (int ks = 0; ks < 2; ++ks) {
        u32 ah[4][4], al[4][4];
        const int arow = lane & 15, acol = ks * 16 + ((lane >> 4) << 3);
        #pragma unroll
        for (int mf = 0; mf < 4; ++mf) {
            const u32 ap = bp + (wm + mf * 16 + arow) * 80 + acol * 2;
            ldm_x4(ah[mf], ap + OAH);
            ldm_x4(al[mf], ap + OAL);
        }
        const int mid = lane >> 3, rr = lane & 7;
        const int brow = ks * 16 + (mid & 1) * 8 + rr;
        #pragma unroll
        for (int np = 0; np < 2; ++np) {
            const int bcol = wn + np * 16 + ((mid >> 1) << 3);
            const u32 bptr = bp + brow * 272 + bcol * 2;
            u32 b[4], c[4];
            ldm_x4t(b, bptr + OBH);
            ldm_x4t(c, bptr + OBL);
            #pragma unroll
            for (int mf = 0; mf < 4; ++mf)
                #pragma unroll
                for (int nq = 0; nq < 2; ++nq) {
                    const int nf = np * 2 + nq;
                    mma16816(acc[mf][nf], ah[mf], b[nq * 2], b[nq * 2 + 1]);
                    mma16816(acc[mf][nf], al[mf], b[nq * 2], b[nq * 2 + 1]);
                    mma16816(acc[mf][nf], ah[mf], c[nq * 2], c[nq * 2 + 1]);
                }
        }
    }
}

// ---------------- GEMM kernels --------------------------------------------------
__global__ __launch_bounds__(256) void k_sffn1() {
    extern __shared__ char smem[];
    const u32 sb = (u32)__cvta_generic_to_shared(smem);
    const int tid = threadIdx.x, w = tid >> 5, lane = tid & 31;
    const int gid = lane >> 2, tig = lane & 3;
    const int m0 = blockIdx.x * 128, n0 = blockIdx.y * 64;
    const int wm = (w >> 2) * 64, wn = (w & 3) * 16;
    float acc1[4][2][4] = {}, acc3[4][2][4] = {};

    const int NCH = DMODEL / 32;
    ffn1_load(sb, g_xh, g_xl, g_s1h, g_s1l, g_s3h, g_s3l, m0, n0, 0, tid, HSH);
    CPCOMMIT();
    for (int ch = 0; ch < NCH; ++ch) {
        if (ch + 1 < NCH) {
            ffn1_load(sb + ((ch + 1) & 1) * S1STG, g_xh, g_xl, g_s1h, g_s1l,
                      g_s3h, g_s3l, m0, n0, (ch + 1) * 32, tid, HSH);
            CPCOMMIT();
            CPWAIT(1);
        } else CPWAIT(0);
        __syncthreads();
        ffn1_mma(sb + (ch & 1) * S1STG, wm, wn, lane, acc1, acc3);
        __syncthreads();
    }
    #pragma unroll
    for (int mf = 0; mf < 4; ++mf)
        #pragma unroll
        for (int nf = 0; nf < 2; ++nf) {
            const int r0 = m0 + wm + mf * 16 + gid;
            const int c0 = n0 + wn + nf * 8 + tig * 2;
            #pragma unroll
            for (int hrow = 0; hrow < 2; ++hrow) {
                const float ox = silu_f(acc1[mf][nf][hrow * 2]) * acc3[mf][nf][hrow * 2];
                const float oy = silu_f(acc1[mf][nf][hrow * 2 + 1]) * acc3[mf][nf][hrow * 2 + 1];
                const size_t off = (size_t)(r0 + hrow * 8) * HSH + c0;
                const u16 hx = bf16h(ox), hy = bf16h(oy);
                *(u32*)(g_hsh + off) = hx | ((u32)hy << 16);
                const u16 lx = bf16h(ox - bf2f(hx)), ly = bf16h(oy - bf2f(hy));
                *(u32*)(g_hsl + off) = lx | ((u32)ly << 16);
            }
        }
}

__global__ __launch_bounds__(256) void k_effn1() {
    const int e = blockIdx.z;
    const int cnt = min(g_cnt[e], CAP);
    const int m0 = blockIdx.x * 128;
    if (m0 >= cnt) return;
    const int n0 = blockIdx.y * 64;
    extern __shared__ char smem[];
    const u32 sb = (u32)__cvta_generic_to_shared(smem);
    const int tid = threadIdx.x, w = tid >> 5, lane = tid & 31;
    const int gid = lane >> 2, tig = lane & 3;
    const int wm = (w >> 2) * 64, wn = (w & 3) * 16;
    const u16* B1h = g_w1h + (size_t)e * DMODEL * HEXP;
    const u16* B1l = g_w1l + (size_t)e * DMODEL * HEXP;
    const u16* B3h = g_w3h + (size_t)e * DMODEL * HEXP;
    const u16* B3l = g_w3l + (size_t)e * DMODEL * HEXP;
    float acc1[4][2][4] = {}, acc3[4][2][4] = {};

    const int NCH = DMODEL / 32;
    ffn1_load_g(sb, g_xh, g_xl, B1h, B1l, B3h, B3l, e, cnt, m0, n0, 0, tid, HEXP);
    CPCOMMIT();
    for (int ch = 0; ch < NCH; ++ch) {
        if (ch + 1 < NCH) {
            ffn1_load_g(sb + ((ch + 1) & 1) * S1STG, g_xh, g_xl, B1h, B1l, B3h, B3l,
                        e, cnt, m0, n0, (ch + 1) * 32, tid, HEXP);
            CPCOMMIT();
            CPWAIT(1);
        } else CPWAIT(0);
        __syncthreads();
        ffn1_mma(sb + (ch & 1) * S1STG, wm, wn, lane, acc1, acc3);
        __syncthreads();
    }
    #pragma unroll
    for (int mf = 0; mf < 4; ++mf)
        #pragma unroll
        for (int nf = 0; nf < 2; ++nf) {
            const int r0 = m0 + wm + mf * 16 + gid;
            const int c0 = n0 + wn + nf * 8 + tig * 2;
            #pragma unroll
            for (int hrow = 0; hrow < 2; ++hrow) {
                if (r0 + hrow * 8 < cnt) {
                    const float ox = silu_f(acc1[mf][nf][hrow * 2]) * acc3[mf][nf][hrow * 2];
                    const float oy = silu_f(acc1[mf][nf][hrow * 2 + 1]) * acc3[mf][nf][hrow * 2 + 1];
                    const size_t off = ((size_t)e * CAP + r0 + hrow * 8) * HEXP + c0;
                    const u16 hx = bf16h(ox), hy = bf16h(oy);
                    *(u32*)(g_hh + off) = hx | ((u32)hy << 16);
                    const u16 lx = bf16h(ox - bf2f(hx)), ly = bf16h(oy - bf2f(hy));
                    *(u32*)(g_hl + off) = lx | ((u32)ly << 16);
                }
            }
        }
}

__global__ __launch_bounds__(256) void k_sffn2(float* __restrict__ out) {
    extern __shared__ char smem[];
    const u32 sb = (u32)__cvta_generic_to_shared(smem);
    const int tid = threadIdx.x, w = tid >> 5, lane = tid & 31;
    const int gid = lane >> 2, tig = lane & 3;
    const int m0 = blockIdx.x * 128, n0 = blockIdx.y * 128;
    const int wm = (w >> 2) * 64, wn = (w & 3) * 32;
    float acc[4][4][4] = {};

    const int NCH = HSH / 32;
    ffn2_load(sb, g_hsh, g_hsl, g_s2h, g_s2l, m0, n0, 0, tid, HSH, DMODEL);
    CPCOMMIT();
    for (int ch = 0; ch < NCH; ++ch) {
        if (ch + 1 < NCH) {
            ffn2_load(sb + ((ch + 1) & 1) * S2STG, g_hsh, g_hsl, g_s2h, g_s2l,
                      m0, n0, (ch + 1) * 32, tid, HSH, DMODEL);
            CPCOMMIT();
            CPWAIT(1);
        } else CPWAIT(0);
        __syncthreads();
        ffn2_mma(sb + (ch & 1) * S2STG, wm, wn, lane, acc);
        __syncthreads();
    }
    #pragma unroll
    for (int mf = 0; mf < 4; ++mf)
        #pragma unroll
        for (int nf = 0; nf < 4; ++nf) {
            const int r0 = m0 + wm + mf * 16 + gid;
            const int c0 = n0 + wn + nf * 8 + tig * 2;
            *(float2*)&out[(size_t)r0 * DMODEL + c0] =
                make_float2(acc[mf][nf][0], acc[mf][nf][1]);
            *(float2*)&out[(size_t)(r0 + 8) * DMODEL + c0] =
                make_float2(acc[mf][nf][2], acc[mf][nf][3]);
        }
}

__global__ __launch_bounds__(256) void k_effn2(float* __restrict__ out) {
    const int e = blockIdx.z;
    const int cnt = min(g_cnt[e], CAP);
    const int m0 = blockIdx.x * 128;
    if (m0 >= cnt) return;
    const int n0 = blockIdx.y * 128;
    extern __shared__ char smem[];
    const u32 sb = (u32)__cvta_generic_to_shared(smem);
    const int tid = threadIdx.x, w = tid >> 5, lane = tid & 31;
    const int gid = lane >> 2, tig = lane & 3;
    const int wm = (w >> 2) * 64, wn = (w & 3) * 32;
    const u16* Bh = g_w2h + (size_t)e * HEXP * DMODEL;
    const u16* Bl = g_w2l + (size_t)e * HEXP * DMODEL;
    float acc[4][4][4] = {};

    const int NCH = HEXP / 32;
    ffn2_load_g(sb, g_hh, g_hl, Bh, Bl, e, cnt, m0, n0, 0, tid, DMODEL);
    CPCOMMIT();
    for (int ch = 0; ch < NCH; ++ch) {
        if (ch + 1 < NCH) {
            ffn2_load_g(sb + ((ch + 1) & 1) * S2STG, g_hh, g_hl, Bh, Bl,
                        e, cnt, m0, n0, (ch + 1) * 32, tid, DMODEL);
            CPCOMMIT();
            CPWAIT(1);
        } else CPWAIT(0);
        __syncthreads();
        ffn2_mma(sb + (ch & 1) * S2STG, wm, wn, lane, acc);
        __syncthreads();
    }
    #pragma unroll
    for (int mf = 0; mf < 4; ++mf) {
        const int r0 = m0 + wm + mf * 16 + gid;
        int   t0v = 0, t1v = 0;
        float w0 = 0.f, w1 = 0.f;
        const bool ok0 = (r0 < cnt), ok1 = (r0 + 8 < cnt);
        if (ok0) { t0v = g_tok[e * CAP + r0];     w0 = g_wgt[e * CAP + r0]; }
        if (ok1) { t1v = g_tok[e * CAP + r0 + 8]; w1 = g_wgt[e * CAP + r0 + 8]; }
        #pragma unroll
        for (int nf = 0; nf < 4; ++nf) {
            const int c0 = n0 + wn + nf * 8 + tig * 2;
            if (ok0) {
                atomicAdd(&out[(size_t)t0v * DMODEL + c0],     w0 * acc[mf][nf][0]);
                atomicAdd(&out[(size_t)t0v * DMODEL + c0 + 1], w0 * acc[mf][nf][1]);
            }
            if (ok1) {
                atomicAdd(&out[(size_t)t1v * DMODEL + c0],     w1 * acc[mf][nf][2]);
                atomicAdd(&out[(size_t)t1v * DMODEL + c0 + 1], w1 * acc[mf][nf][3]);
            }
        }
    }
}

// ---------------- launch ---------------------------------------------------------
extern "C" void kernel_launch(void* const* d_in, const int* in_sizes, int n_in,
                              void* d_out, int out_size) {
    const float* x    = (const float*)d_in[0];
    const float* gate = (const float*)d_in[1];
    const float* w1   = (const float*)d_in[2];
    const float* w3   = (const float*)d_in[3];
    const float* w2   = (const float*)d_in[4];
    const float* sw1  = (const float*)d_in[5];
    const float* sw3  = (const float*)d_in[6];
    const float* sw2  = (const float*)d_in[7];
    float* out = (float*)d_out;

    u16 *xh, *xl, *w1h, *w1l, *w3h, *w3l, *w2h, *w2l;
    u16 *s1h, *s1l, *s3h, *s3l, *s2h, *s2l;
    cudaGetSymbolAddress((void**)&xh,  g_xh);  cudaGetSymbolAddress((void**)&xl,  g_xl);
    cudaGetSymbolAddress((void**)&w1h, g_w1h); cudaGetSymbolAddress((void**)&w1l, g_w1l);
    cudaGetSymbolAddress((void**)&w3h, g_w3h); cudaGetSymbolAddress((void**)&w3l, g_w3l);
    cudaGetSymbolAddress((void**)&w2h, g_w2h); cudaGetSymbolAddress((void**)&w2l, g_w2l);
    cudaGetSymbolAddress((void**)&s1h, g_s1h); cudaGetSymbolAddress((void**)&s1l, g_s1l);
    cudaGetSymbolAddress((void**)&s3h, g_s3h); cudaGetSymbolAddress((void**)&s3l, g_s3l);
    cudaGetSymbolAddress((void**)&s2h, g_s2h); cudaGetSymbolAddress((void**)&s2l, g_s2l);

    cudaFuncSetAttribute(k_sffn1, cudaFuncAttributeMaxDynamicSharedMemorySize, 2 * S1STG);
    cudaFuncSetAttribute(k_effn1, cudaFuncAttributeMaxDynamicSharedMemorySize, 2 * S1STG);
    cudaFuncSetAttribute(k_sffn2, cudaFuncAttributeMaxDynamicSharedMemorySize, 2 * S2STG);
    cudaFuncSetAttribute(k_effn2, cudaFuncAttributeMaxDynamicSharedMemorySize, 2 * S2STG);

    k_zero<<<1, 64>>>();
    k_router<<<NTOK / RTB, 128>>>(x, gate);

    const int NW = NEXP * DMODEL * HEXP;   // 8.39M
    k_cvt<<<NTOK * DMODEL / 8 / 256, 256>>>(x, xh, xl, NTOK * DMODEL);
    k_cvt<<<NW / 8 / 256, 256>>>(w1, w1h, w1l, NW);
    k_cvt<<<NW / 8 / 256, 256>>>(w3, w3h, w3l, NW);
    k_cvt<<<NW / 8 / 256, 256>>>(w2, w2h, w2l, NW);
    k_cvt<<<DMODEL * HSH / 8 / 256, 256>>>(sw1, s1h, s1l, DMODEL * HSH);
    k_cvt<<<DMODEL * HSH / 8 / 256, 256>>>(sw3, s3h, s3l, DMODEL * HSH);
    k_cvt<<<DMODEL * HSH / 8 / 256, 256>>>(sw2, s2h, s2l, DMODEL * HSH);

    k_sffn1<<<dim3(NTOK / 128, HSH / 64), 256, 2 * S1STG>>>();
    k_effn1<<<dim3(CAP / 128, HEXP / 64, NEXP), 256, 2 * S1STG>>>();
    k_sffn2<<<dim3(NTOK / 128, DMODEL / 128), 256, 2 * S2STG>>>(out);
    k_effn2<<<dim3(CAP / 128, DMODEL / 128, NEXP), 256, 2 * S2STG>>>(out);
}